// round 17
// baseline (speedup 1.0000x reference)
#include <cuda_runtime.h>
#include <cuda_bf16.h>
#include <math.h>

#define BB 16
#define NN 4096
#define SS 1024
#define KK 32
#define GG (BB*SS)            // 16384 groups
#define MAXP (GG*KK)          // 524288 worst-case positions
#define TOTAL_DIV 524288.0    // BN divisor: B*K*S (= 2^19, exact fp scaling)

// ---------------- scratch (static device globals; no runtime allocation) ----
__device__ float  g_x0[(size_t)MAXP * 8];     // compacted input features (padded to 8 ch)
__device__ float  g_wt[MAXP];                  // multiplicity weight per position
__device__ int    g_gstart[GG];
__device__ int    g_gcnt[GG];
__device__ int    g_ptot;
__device__ float  g_y1[(size_t)MAXP * 64];
__device__ float  g_y2[(size_t)MAXP * 64];
__device__ float  g_y3[(size_t)MAXP * 128];
__device__ double g_sum[3][128];
__device__ double g_sumsq[3][128];

// ---------------- packed f32x2 helpers (per-lane .rn semantics == scalar) ---
__device__ __forceinline__ unsigned long long f2_pack(float lo, float hi) {
    unsigned long long r;
    asm("mov.b64 %0, {%1, %2};" : "=l"(r) : "f"(lo), "f"(hi));
    return r;
}
__device__ __forceinline__ void f2_unpack(unsigned long long v, float& lo, float& hi) {
    asm("mov.b64 {%0, %1}, %2;" : "=f"(lo), "=f"(hi) : "l"(v));
}
__device__ __forceinline__ unsigned long long f2_add(unsigned long long a, unsigned long long b) {
    unsigned long long r;
    asm("add.rn.f32x2 %0, %1, %2;" : "=l"(r) : "l"(a), "l"(b));
    return r;
}
__device__ __forceinline__ unsigned long long f2_mul(unsigned long long a, unsigned long long b) {
    unsigned long long r;
    asm("mul.rn.f32x2 %0, %1, %2;" : "=l"(r) : "l"(a), "l"(b));
    return r;
}

// ---------------- farthest point sampling (bit-exact) -----------------------
// one block per batch, 256 threads, 16 points/thread (8 f32x2 pairs).
// Block 0 additionally zeroes the global accumulators.
__global__ __launch_bounds__(256, 1)
void fps_kernel(const float* __restrict__ xyz, float* __restrict__ newxyz) {
    int b = blockIdx.x, tid = threadIdx.x;
    const float* bx = xyz + (size_t)b * 3 * NN;

    if (b == 0) {
        if (tid == 0) g_ptot = 0;
        for (int t = tid; t < 384; t += 256) {
            ((double*)g_sum)[t]   = 0.0;
            ((double*)g_sumsq)[t] = 0.0;
        }
    }

    unsigned long long px2[8], py2[8], pz2[8];
    float dist[16];
    {
        const float4* x4 = (const float4*)(bx);
        const float4* y4 = (const float4*)(bx + NN);
        const float4* z4 = (const float4*)(bx + 2 * NN);
#pragma unroll
        for (int h = 0; h < 4; h++) {
            float4 xa = x4[tid * 4 + h], ya = y4[tid * 4 + h], za = z4[tid * 4 + h];
            px2[2*h]   = f2_pack(xa.x, xa.y);
            px2[2*h+1] = f2_pack(xa.z, xa.w);
            py2[2*h]   = f2_pack(ya.x, ya.y);
            py2[2*h+1] = f2_pack(ya.z, ya.w);
            pz2[2*h]   = f2_pack(za.x, za.y);
            pz2[2*h+1] = f2_pack(za.z, za.w);
        }
    }
#pragma unroll
    for (int j = 0; j < 16; j++) dist[j] = 1e10f;

    __shared__ unsigned long long skey[2][8];   // {bits<<32 | widx} per warp
    __shared__ int fhist[SS];
    int lane = tid & 31, wid = tid >> 5;
    int farthest = 0;

    for (int it = 0; it < SS; ++it) {
        if (tid == 0) fhist[it] = farthest;
        float cx = __ldg(bx + farthest);
        float cy = __ldg(bx + NN + farthest);
        float cz = __ldg(bx + 2 * NN + farthest);
        unsigned long long ncx = f2_pack(-cx, -cx);
        unsigned long long ncy = f2_pack(-cy, -cy);
        unsigned long long ncz = f2_pack(-cz, -cz);

        // packed distance update: per lane rn(sub), rn(mul), rn((xx+yy)+zz)
#pragma unroll
        for (int k = 0; k < 8; k++) {
            unsigned long long dx = f2_add(px2[k], ncx);
            unsigned long long dy = f2_add(py2[k], ncy);
            unsigned long long dz = f2_add(pz2[k], ncz);
            unsigned long long s  = f2_add(f2_add(f2_mul(dx, dx), f2_mul(dy, dy)),
                                           f2_mul(dz, dz));
            float d0, d1;
            f2_unpack(s, d0, d1);
            dist[2*k]   = fminf(dist[2*k],   d0);
            dist[2*k+1] = fminf(dist[2*k+1], d1);
        }

        // local argmax tree over 16, first-index ties (strict > keeps lower)
        float v1[8]; int i1[8];
#pragma unroll
        for (int k = 0; k < 8; k++) {
            bool g = dist[2*k+1] > dist[2*k];
            v1[k] = g ? dist[2*k+1] : dist[2*k];
            i1[k] = g ? 2*k+1 : 2*k;
        }
        float v2[4]; int i2[4];
#pragma unroll
        for (int k = 0; k < 4; k++) {
            bool g = v1[2*k+1] > v1[2*k];
            v2[k] = g ? v1[2*k+1] : v1[2*k];
            i2[k] = g ? i1[2*k+1] : i1[2*k];
        }
        bool g0 = v2[1] > v2[0];
        float va = g0 ? v2[1] : v2[0]; int ia = g0 ? i2[1] : i2[0];
        bool g1 = v2[3] > v2[2];
        float vb = g1 ? v2[3] : v2[2]; int ib = g1 ? i2[3] : i2[2];
        bool g2 = vb > va;
        float bv = g2 ? vb : va;
        int bi = tid * 16 + (g2 ? ib : ia);

        // warp argmax via REDUX on float bits (dists >= 0 -> u32 monotone)
        unsigned bits = __float_as_uint(bv);
        unsigned wmax = __reduce_max_sync(0xffffffffu, bits);
        unsigned mm   = __ballot_sync(0xffffffffu, bits == wmax);
        int src  = __ffs(mm) - 1;                 // lowest lane = lowest index
        int widx = __shfl_sync(0xffffffffu, bi, src);

        int buf = it & 1;
        if (lane == 0)
            skey[buf][wid] = ((unsigned long long)wmax << 32) | (unsigned)widx;
        __syncthreads();

        // block argmax over 8 warp winners (lowest-wid first-index tiebreak)
        unsigned long long e = skey[buf][lane & 7];
        unsigned eb   = (unsigned)(e >> 32);
        int      ei   = (int)(unsigned)e;
        unsigned bmax = __reduce_max_sync(0xffffffffu, eb);
        unsigned wm   = __ballot_sync(0xffffffffu, eb == bmax);
        int fl = __ffs(wm) - 1;
        farthest = __shfl_sync(0xffffffffu, ei, fl);
    }

    // bulk centroid write-out
    __syncthreads();
    for (int i = tid; i < SS; i += 256) {
        int idx = fhist[i];
        newxyz[(size_t)b * 3 * SS + i]          = __ldg(bx + idx);
        newxyz[(size_t)b * 3 * SS + SS + i]     = __ldg(bx + NN + idx);
        newxyz[(size_t)b * 3 * SS + 2 * SS + i] = __ldg(bx + 2 * NN + idx);
    }
}

// ---------------- ball query + compaction + gather --------------------------
// one warp per group (b, s); four points per lane via float4 loads.
// Distance matches the reference's fp32 arithmetic op-for-op.
__global__ __launch_bounds__(128)
void query_gather_kernel(const float* __restrict__ xyz,
                         const float* __restrict__ pts,
                         const float* __restrict__ newxyz) {
    int gwarp = (blockIdx.x * blockDim.x + threadIdx.x) >> 5;
    int lane  = threadIdx.x & 31;
    int wslot = (threadIdx.x >> 5) & 3;
    int b = gwarp >> 10, s = gwarp & (SS - 1);

    __shared__ int sgidx[4][KK];
    int* gidx = sgidx[wslot];

    const float* bx = xyz + (size_t)b * 3 * NN;
    float cx = newxyz[(size_t)b * 3 * SS + s];
    float cy = newxyz[(size_t)b * 3 * SS + SS + s];
    float cz = newxyz[(size_t)b * 3 * SS + 2 * SS + s];
    float ns = __fadd_rn(__fadd_rn(__fmul_rn(cx, cx), __fmul_rn(cy, cy)),
                         __fmul_rn(cz, cz));

    unsigned below = (1u << lane) - 1u;
    int cnt = 0;
    for (int j = 0; j < NN / 128; j++) {
        int i0 = j * 128 + 4 * lane;
        float4 X = *(const float4*)(bx + i0);
        float4 Y = *(const float4*)(bx + NN + i0);
        float4 Z = *(const float4*)(bx + 2 * NN + i0);

        float xs[4] = {X.x, X.y, X.z, X.w};
        float ys[4] = {Y.x, Y.y, Y.z, Y.w};
        float zs[4] = {Z.x, Z.y, Z.z, Z.w};
        bool ok[4];
#pragma unroll
        for (int k = 0; k < 4; k++) {
            float nd = __fadd_rn(__fadd_rn(__fmul_rn(xs[k], xs[k]),
                                           __fmul_rn(ys[k], ys[k])),
                                 __fmul_rn(zs[k], zs[k]));
            float t  = __fmaf_rn(cz, zs[k], __fmaf_rn(cy, ys[k], __fmul_rn(cx, xs[k])));
            float d  = __fadd_rn(__fadd_rn(__fmul_rn(-2.0f, t), ns), nd);
            ok[k] = !(d > 0.04f);
        }
        unsigned m0 = __ballot_sync(0xffffffffu, ok[0]);
        unsigned m1 = __ballot_sync(0xffffffffu, ok[1]);
        unsigned m2 = __ballot_sync(0xffffffffu, ok[2]);
        unsigned m3 = __ballot_sync(0xffffffffu, ok[3]);
        int pos = cnt + __popc(m0 & below) + __popc(m1 & below)
                      + __popc(m2 & below) + __popc(m3 & below);
#pragma unroll
        for (int k = 0; k < 4; k++) {
            if (ok[k]) {
                if (pos < KK) gidx[pos] = i0 + k;
                pos++;
            }
        }
        cnt += __popc(m0) + __popc(m1) + __popc(m2) + __popc(m3);
        if (cnt >= KK) break;
    }
    int mcnt = min(cnt, KK);
    __syncwarp();

    int base = 0;
    if (lane == 0) {
        base = atomicAdd(&g_ptot, mcnt);
        g_gstart[gwarp] = base;
        g_gcnt[gwarp]   = mcnt;
    }
    base = __shfl_sync(0xffffffffu, base, 0);

    if (lane < mcnt) {
        int i = gidx[lane];
        const float* bp = pts + (size_t)b * 3 * NN;
        float* dst = g_x0 + (size_t)(base + lane) * 8;
        dst[0] = __fsub_rn(bx[i], cx);
        dst[1] = __fsub_rn(bx[NN + i], cy);
        dst[2] = __fsub_rn(bx[2 * NN + i], cz);
        dst[3] = bp[i];
        dst[4] = bp[NN + i];
        dst[5] = bp[2 * NN + i];
        dst[6] = 0.0f;
        dst[7] = 0.0f;
        g_wt[base + lane] = (lane == 0) ? (float)(KK - mcnt + 1) : 1.0f;
    }
}

// ---------------- unified GEMM + fused input-affine + output stats -----------
// 256 threads/block; tile = 128 positions (COUT=64) or 64 (COUT=128).
// BN affine params live in registers (each thread's fill c-quad is fixed
// because NC4 divides 256); stats scratch aliases Xs after the main loop,
// keeping static smem at exactly 48KB for the largest instantiation.
template<int CIN, int COUT, int LOUT>
__global__ __launch_bounds__(256)
void gemm_stats_kernel(const float* __restrict__ W,
                       const float* __restrict__ gamma,
                       const float* __restrict__ beta) {
    constexpr bool BN_IN = (LOUT > 0);
    constexpr int TILE = (COUT == 64) ? 128 : 64;
    constexpr int TX = COUT / 8;           // 8 or 16
    constexpr int TY = 256 / TX;           // 32 or 16
    constexpr int PT = TILE / TY;          // 4
    constexpr int HALF = COUT / 2;
    constexpr int NC4 = CIN / 4;           // 2 or 16 (divides 256)

    __shared__ float Xs[TILE * CIN];       // [pos][c]; aliased for stats at end
    __shared__ float Ws[CIN * COUT];       // [c][o]

    const float* Yin  = (LOUT == 0) ? g_x0 : (LOUT == 1 ? g_y1 : g_y2);
    float*       Yout = (LOUT == 0) ? g_y1 : (LOUT == 1 ? g_y2 : g_y3);

    int tid = threadIdx.x;
    int tx = tid % TX, ty = tid / TX;
    int myc4 = tid % NC4;

    for (int idx = tid; idx < CIN * COUT; idx += 256) {
        int c = idx % CIN, o = idx / CIN;
        float w;
        if (LOUT == 0) w = (c < 6) ? W[o * 6 + c] : 0.0f;   // W is (64, 6)
        else           w = W[o * 64 + c];                    // W is (COUT, 64)
        Ws[c * COUT + o] = w;
    }

    // register-resident BN affine for this thread's fixed fill quad
    float rA[4], rB[4];
    if (BN_IN) {
#pragma unroll
        for (int k = 0; k < 4; k++) {
            int c = myc4 * 4 + k;
            double dmean = g_sum[LOUT - 1][c] * (1.0 / TOTAL_DIV);   // exact /2^19
            double dvar  = g_sumsq[LOUT - 1][c] * (1.0 / TOTAL_DIV) - dmean * dmean;
            float inv = 1.0f / sqrtf((float)dvar + 1e-5f);
            float Aa  = gamma[c] * inv;
            rA[k] = Aa;
            rB[k] = beta[c] - (float)dmean * Aa;
        }
    }
    __syncthreads();

    float ps[8], pq[8];
#pragma unroll
    for (int i = 0; i < 8; i++) { ps[i] = 0.0f; pq[i] = 0.0f; }

    int ptot = g_ptot;
    int ntiles = (ptot + TILE - 1) / TILE;
    for (int t = blockIdx.x; t < ntiles; t += gridDim.x) {
        int p0 = t * TILE;
        // float4 tile fill; q % NC4 == myc4 always (NC4 | 256)
#pragma unroll 2
        for (int q = tid; q < TILE * NC4; q += 256) {
            int pl = q / NC4;
            int p = p0 + pl;
            float4 v = make_float4(0.f, 0.f, 0.f, 0.f);
            if (p < ptot) {
                v = *(const float4*)(Yin + (size_t)p * CIN + myc4 * 4);
                if (BN_IN) {
                    v.x = fmaxf(fmaf(rA[0], v.x, rB[0]), 0.0f);
                    v.y = fmaxf(fmaf(rA[1], v.y, rB[1]), 0.0f);
                    v.z = fmaxf(fmaf(rA[2], v.z, rB[2]), 0.0f);
                    v.w = fmaxf(fmaf(rA[3], v.w, rB[3]), 0.0f);
                }
            }
            *(float4*)(Xs + pl * CIN + myc4 * 4) = v;
        }
        __syncthreads();

        float acc[PT][8];
#pragma unroll
        for (int j = 0; j < PT; j++)
#pragma unroll
            for (int i = 0; i < 8; i++) acc[j][i] = 0.0f;

#pragma unroll
        for (int c = 0; c < CIN; c++) {
            float4 wa = *(const float4*)(Ws + c * COUT + tx * 4);
            float4 wb = *(const float4*)(Ws + c * COUT + HALF + tx * 4);
            float xv[PT];
#pragma unroll
            for (int j = 0; j < PT; j++) xv[j] = Xs[(ty * PT + j) * CIN + c];
#pragma unroll
            for (int j = 0; j < PT; j++) {
                acc[j][0] = fmaf(xv[j], wa.x, acc[j][0]);
                acc[j][1] = fmaf(xv[j], wa.y, acc[j][1]);
                acc[j][2] = fmaf(xv[j], wa.z, acc[j][2]);
                acc[j][3] = fmaf(xv[j], wa.w, acc[j][3]);
                acc[j][4] = fmaf(xv[j], wb.x, acc[j][4]);
                acc[j][5] = fmaf(xv[j], wb.y, acc[j][5]);
                acc[j][6] = fmaf(xv[j], wb.z, acc[j][6]);
                acc[j][7] = fmaf(xv[j], wb.w, acc[j][7]);
            }
        }

#pragma unroll
        for (int j = 0; j < PT; j++) {
            int p = p0 + ty * PT + j;
            if (p < ptot) {
                float w = g_wt[p];
                float4 o0 = make_float4(acc[j][0], acc[j][1], acc[j][2], acc[j][3]);
                float4 o1 = make_float4(acc[j][4], acc[j][5], acc[j][6], acc[j][7]);
                *(float4*)(Yout + (size_t)p * COUT + tx * 4) = o0;
                *(float4*)(Yout + (size_t)p * COUT + HALF + tx * 4) = o1;
#pragma unroll
                for (int i = 0; i < 8; i++) {
                    float v = acc[j][i];
                    float wv = w * v;
                    ps[i] += wv;
                    pq[i] += wv * v;
                }
            }
        }
        __syncthreads();
    }

    // stats reduction: scratch aliases Xs (main loop done)
    float* ssum = Xs;
    float* ssq  = Xs + COUT;
    if (tid < COUT) { ssum[tid] = 0.0f; ssq[tid] = 0.0f; }
    __syncthreads();
#pragma unroll
    for (int i = 0; i < 8; i++) {
        int ch = (i < 4) ? (tx * 4 + i) : (HALF + tx * 4 + (i - 4));
        atomicAdd(&ssum[ch], ps[i]);
        atomicAdd(&ssq[ch],  pq[i]);
    }
    __syncthreads();
    if (tid < COUT) {
        atomicAdd(&g_sum[LOUT][tid],   (double)ssum[tid]);
        atomicAdd(&g_sumsq[LOUT][tid], (double)ssq[tid]);
    }
}

// ---------------- final BN+ReLU + max over group (affine inlined) ------------
__global__ __launch_bounds__(128)
void maxpool_kernel(const float* __restrict__ gamma,
                    const float* __restrict__ beta,
                    float* __restrict__ feats) {
    int g = blockIdx.x;
    int o = threadIdx.x;               // 128
    // per-block redundant affine (deterministic; g_sum[2] is L2-resident)
    double dmean = g_sum[2][o] * (1.0 / TOTAL_DIV);
    double dvar  = g_sumsq[2][o] * (1.0 / TOTAL_DIV) - dmean * dmean;
    float inv = 1.0f / sqrtf((float)dvar + 1e-5f);
    float Aa  = gamma[o] * inv;
    float Bb  = beta[o] - (float)dmean * Aa;

    int m  = g_gcnt[g];
    int st = g_gstart[g];
    float mx = -3.4e38f;
    for (int k = 0; k < m; k++) {
        float y = g_y3[(size_t)(st + k) * 128 + o];
        float z = fmaxf(fmaf(Aa, y, Bb), 0.0f);
        mx = fmaxf(mx, z);
    }
    int b = g >> 10, s = g & (SS - 1);
    feats[((size_t)b * 128 + o) * SS + s] = mx;
}

// ---------------- launch ----------------------------------------------------
extern "C" void kernel_launch(void* const* d_in, const int* in_sizes, int n_in,
                              void* d_out, int out_size) {
    const float* xyz = (const float*)d_in[0];
    const float* pts = (const float*)d_in[1];
    const float* w0  = (const float*)d_in[2];
    const float* g0  = (const float*)d_in[4];
    const float* be0 = (const float*)d_in[5];
    const float* w1  = (const float*)d_in[6];
    const float* g1  = (const float*)d_in[8];
    const float* be1 = (const float*)d_in[9];
    const float* w2  = (const float*)d_in[10];
    const float* g2  = (const float*)d_in[12];
    const float* be2 = (const float*)d_in[13];

    float* out    = (float*)d_out;
    float* newxyz = out;                              // (B,3,S)
    float* feats  = out + (size_t)BB * 3 * SS;        // (B,128,S)

    fps_kernel<<<BB, 256>>>(xyz, newxyz);             // also zeroes accumulators
    query_gather_kernel<<<GG / 4, 128>>>(xyz, pts, newxyz);

    gemm_stats_kernel<8, 64, 0><<<256, 256>>>(w0, g0, be0);
    gemm_stats_kernel<64, 64, 1><<<256, 256>>>(w1, g0, be0);   // affine of layer 0
    gemm_stats_kernel<64, 128, 2><<<256, 256>>>(w2, g1, be1);  // affine of layer 1

    maxpool_kernel<<<GG, 128>>>(g2, be2, feats);
}